// round 16
// baseline (speedup 1.0000x reference)
#include <cuda_runtime.h>
#include <cstdint>

// Problem constants (fixed by the dataset: x [32,256,512], embeddings [8192,512])
#define N_TOK   8192
#define K_CODES 8192
#define DIM     512

// Approx pass tiling
#define BM 128
#define BN 128
#define BD 32
#define NSTAGE (DIM / BD)      // 16
#define XSTR 36                // row stride (floats): (lane>>2)*36 + (lane&3) -> 4g+i mod 32, conflict-free
#define SPLITS2 64             // one split per 128-code block column
#define KS2 128
#define MARGIN 1e-3f           // sound bound: worst-case approx-vs-exact skew <= 4.4e-4

// ---------------- device scratch (no allocations allowed) ----------------
// Referenced ONLY from device code (host-side use of a __device__ symbol is the
// host shadow address -> UVM pool allocation -> harness mem-guard failure).
__device__ float g_esq[K_CODES];
__device__ float g_xsq[N_TOK];
__device__ float g_pval2[SPLITS2][N_TOK];   // approx per-(split,row) min value
__device__ int   g_fidx[N_TOK];             // exact final argmin index
__device__ float g_rowsq[N_TOK];

// tf32 input rounding (b32 destination register).
__device__ __forceinline__ uint32_t tf32u(float a) {
    uint32_t r;
    asm("cvt.rna.tf32.f32 %0, %1;" : "=r"(r) : "f"(a));
    return r;
}

__device__ __forceinline__ void mma_tf32(float* c, const uint32_t* a, uint32_t b0, uint32_t b1) {
    asm volatile(
        "mma.sync.aligned.m16n8k8.row.col.f32.tf32.tf32.f32 "
        "{%0,%1,%2,%3}, {%4,%5,%6,%7}, {%8,%9}, {%0,%1,%2,%3};"
        : "+f"(c[0]), "+f"(c[1]), "+f"(c[2]), "+f"(c[3])
        : "r"(a[0]), "r"(a[1]), "r"(a[2]), "r"(a[3]), "r"(b0), "r"(b1));
}

// ---------------- kernel 1a: e_sq[k] = sum_d E[k][d]^2 ----------------
// XLA row-reduce replica (verified bit-exact R9-R15): lane-strided ascending,
// NON-FUSED mul+add, butterfly tree.
__global__ void vq_esq(const float* __restrict__ E) {
    int w = (blockIdx.x * blockDim.x + threadIdx.x) >> 5;
    int lane = threadIdx.x & 31;
    if (w >= K_CODES) return;
    const float* row = E + (size_t)w * DIM;
    float s = 0.f;
    #pragma unroll
    for (int d = lane; d < DIM; d += 32) {
        float v = __ldg(row + d);
        s = __fadd_rn(s, __fmul_rn(v, v));
    }
    #pragma unroll
    for (int o = 16; o > 0; o >>= 1) s = __fadd_rn(s, __shfl_xor_sync(0xffffffffu, s, o));
    if (lane == 0) g_esq[w] = s;
}

// ---------------- kernel 1b: x_sq[n] = sum_d x[n][d]^2 ----------------
__global__ void vq_xsq(const float* __restrict__ x) {
    int w = (blockIdx.x * blockDim.x + threadIdx.x) >> 5;
    int lane = threadIdx.x & 31;
    if (w >= N_TOK) return;
    const float* row = x + (size_t)w * DIM;
    float s = 0.f;
    #pragma unroll
    for (int d = lane; d < DIM; d += 32) {
        float v = __ldg(row + d);
        s = __fadd_rn(s, __fmul_rn(v, v));
    }
    #pragma unroll
    for (int o = 16; o > 0; o >>= 1) s = __fadd_rn(s, __shfl_xor_sync(0xffffffffu, s, o));
    if (lane == 0) g_xsq[w] = s;
}

// ---------------- kernel 2: APPROX pass — tf32 tensor-core partial mins ----------------
// Grid (64 ktile, 64 mtile), 256 threads = 8 warps as 4(m) x 2(n).
// Warp tile 32 rows x 64 codes: 2 m-frags x 8 n-frags of m16n8k8.
// Emits g_pval2[ktile][row] = min over 128 codes of (e_sq[k] - 2*dot_tf32).
// Accuracy is NOT required here; MARGIN in the exact pass covers all error.
__global__ __launch_bounds__(256) void vq_approx(const float* __restrict__ x,
                                                 const float* __restrict__ E) {
    __shared__ float xs[BM][XSTR];
    __shared__ float es[BN][XSTR];

    const int t = threadIdx.x;
    const int lane = t & 31;
    const int wid = t >> 5;
    const int wm = wid >> 1;       // 0..3
    const int wn = wid & 1;        // 0..1
    const int m0 = blockIdx.y * BM;
    const int k0 = blockIdx.x * BN;
    const int lrow  = t >> 1;
    const int lhalf = (t & 1) * 16;
    const int qr = lane >> 2;      // 0..7
    const int qc = lane & 3;       // 0..3

    float acc[2][8][4];
    #pragma unroll
    for (int f = 0; f < 2; f++)
        #pragma unroll
        for (int g = 0; g < 8; g++)
            #pragma unroll
            for (int j = 0; j < 4; j++) acc[f][g][j] = 0.f;

    for (int s = 0; s < NSTAGE; s++) {
        const int d0 = s * BD;
        __syncthreads();
        {   // stage tiles (tf32-converted)
            const float* xp = &x[(size_t)(m0 + lrow) * DIM + d0 + lhalf];
            const float* ep = &E[(size_t)(k0 + lrow) * DIM + d0 + lhalf];
            #pragma unroll
            for (int v4 = 0; v4 < 4; v4++) {
                float4 a = *reinterpret_cast<const float4*>(xp + 4 * v4);
                uint4 ua = make_uint4(tf32u(a.x), tf32u(a.y), tf32u(a.z), tf32u(a.w));
                *reinterpret_cast<uint4*>(&xs[lrow][lhalf + 4 * v4]) = ua;
                float4 b = *reinterpret_cast<const float4*>(ep + 4 * v4);
                uint4 ub = make_uint4(tf32u(b.x), tf32u(b.y), tf32u(b.z), tf32u(b.w));
                *reinterpret_cast<uint4*>(&es[lrow][lhalf + 4 * v4]) = ub;
            }
        }
        __syncthreads();
        #pragma unroll
        for (int ks = 0; ks < 4; ks++) {
            const int c = ks * 8 + qc;
            uint32_t afr[2][4];
            #pragma unroll
            for (int f = 0; f < 2; f++) {
                int r = wm * 32 + f * 16 + qr;
                afr[f][0] = __float_as_uint(xs[r][c]);
                afr[f][1] = __float_as_uint(xs[r + 8][c]);
                afr[f][2] = __float_as_uint(xs[r][c + 4]);
                afr[f][3] = __float_as_uint(xs[r + 8][c + 4]);
            }
            #pragma unroll
            for (int g = 0; g < 8; g++) {
                int n = wn * 64 + g * 8 + qr;
                uint32_t b0 = __float_as_uint(es[n][c]);
                uint32_t b1 = __float_as_uint(es[n][c + 4]);
                mma_tf32(acc[0][g], afr[0], b0, b1);
                mma_tf32(acc[1][g], afr[1], b0, b1);
            }
        }
    }

    // epilogue: per-thread row mins over this warp's 64 codes
    float rmin[2][2] = {{3.4e38f, 3.4e38f}, {3.4e38f, 3.4e38f}};
    #pragma unroll
    for (int f = 0; f < 2; f++)
        #pragma unroll
        for (int g = 0; g < 8; g++) {
            int n0 = k0 + wn * 64 + g * 8 + 2 * qc;
            float eq0 = __ldg(&g_esq[n0]);
            float eq1 = __ldg(&g_esq[n0 + 1]);
            float s00 = eq0 - 2.f * acc[f][g][0];
            float s01 = eq1 - 2.f * acc[f][g][1];
            float s10 = eq0 - 2.f * acc[f][g][2];
            float s11 = eq1 - 2.f * acc[f][g][3];
            rmin[f][0] = fminf(rmin[f][0], fminf(s00, s01));
            rmin[f][1] = fminf(rmin[f][1], fminf(s10, s11));
        }
    // reduce over the quad (lane&3)
    #pragma unroll
    for (int o = 1; o <= 2; o <<= 1) {
        #pragma unroll
        for (int f = 0; f < 2; f++)
            #pragma unroll
            for (int h = 0; h < 2; h++)
                rmin[f][h] = fminf(rmin[f][h], __shfl_xor_sync(0xffffffffu, rmin[f][h], o));
    }
    __syncthreads();                       // tiles dead, reuse xs as [128][2]
    float* pm = &xs[0][0];
    if (qc == 0) {
        #pragma unroll
        for (int f = 0; f < 2; f++)
            #pragma unroll
            for (int h = 0; h < 2; h++) {
                int row = wm * 32 + f * 16 + h * 8 + qr;
                pm[row * 2 + wn] = rmin[f][h];
            }
    }
    __syncthreads();
    if (t < BM)
        g_pval2[blockIdx.x][m0 + t] = fminf(pm[t * 2], pm[t * 2 + 1]);
}

// ---------------- kernel 3: EXACT rescue — re-evaluate candidate splits ----------------
// One warp per row. Any split whose approx min < gmin + MARGIN is re-scored with
// the verbatim reference pipeline: serial ascending-d fp32 FMA chain per code,
// dist = fl( fl(x_sq - 2*dot) + e_sq ), strict < ascending k, min-idx ties.
__global__ __launch_bounds__(256) void vq_exact(const float* __restrict__ x,
                                                const float* __restrict__ E) {
    __shared__ float xrow_s[8][DIM];
    const int wid = threadIdx.x >> 5;
    const int lane = threadIdx.x & 31;
    const int row = blockIdx.x * 8 + wid;

    // stage this row of x
    const float* xr = x + (size_t)row * DIM;
    #pragma unroll
    for (int i = lane; i < DIM / 4; i += 32)
        reinterpret_cast<float4*>(xrow_s[wid])[i] = reinterpret_cast<const float4*>(xr)[i];
    __syncwarp();

    float gv = fminf(g_pval2[lane][row], g_pval2[lane + 32][row]);
    #pragma unroll
    for (int o = 16; o > 0; o >>= 1) gv = fminf(gv, __shfl_xor_sync(0xffffffffu, gv, o));
    const float thresh = gv + MARGIN;
    const float xsq = g_xsq[row];

    float bestv = 3.4e38f;
    int   besti = 0;

    for (int s = 0; s < SPLITS2; s++) {
        if (!(g_pval2[s][row] < thresh)) continue;
        const int kb = s * KS2 + lane;            // lane's codes: kb, kb+32, kb+64, kb+96
        const float* e0 = E + (size_t)kb * DIM;
        const float* e1 = e0 + (size_t)32 * DIM;
        const float* e2 = e0 + (size_t)64 * DIM;
        const float* e3 = e0 + (size_t)96 * DIM;
        float a0 = 0.f, a1 = 0.f, a2 = 0.f, a3 = 0.f;
        #pragma unroll 4
        for (int d = 0; d < DIM; d += 4) {
            float4 xv = *reinterpret_cast<const float4*>(&xrow_s[wid][d]);
            float4 v0 = *reinterpret_cast<const float4*>(e0 + d);
            float4 v1 = *reinterpret_cast<const float4*>(e1 + d);
            float4 v2 = *reinterpret_cast<const float4*>(e2 + d);
            float4 v3 = *reinterpret_cast<const float4*>(e3 + d);
            a0 = fmaf(xv.x, v0.x, a0); a0 = fmaf(xv.y, v0.y, a0);
            a0 = fmaf(xv.z, v0.z, a0); a0 = fmaf(xv.w, v0.w, a0);
            a1 = fmaf(xv.x, v1.x, a1); a1 = fmaf(xv.y, v1.y, a1);
            a1 = fmaf(xv.z, v1.z, a1); a1 = fmaf(xv.w, v1.w, a1);
            a2 = fmaf(xv.x, v2.x, a2); a2 = fmaf(xv.y, v2.y, a2);
            a2 = fmaf(xv.z, v2.z, a2); a2 = fmaf(xv.w, v2.w, a2);
            a3 = fmaf(xv.x, v3.x, a3); a3 = fmaf(xv.y, v3.y, a3);
            a3 = fmaf(xv.z, v3.z, a3); a3 = fmaf(xv.w, v3.w, a3);
        }
        float sc;
        sc = __fadd_rn(fmaf(-2.f, a0, xsq), __ldg(&g_esq[kb]));
        if (sc < bestv) { bestv = sc; besti = kb; }
        sc = __fadd_rn(fmaf(-2.f, a1, xsq), __ldg(&g_esq[kb + 32]));
        if (sc < bestv) { bestv = sc; besti = kb + 32; }
        sc = __fadd_rn(fmaf(-2.f, a2, xsq), __ldg(&g_esq[kb + 64]));
        if (sc < bestv) { bestv = sc; besti = kb + 64; }
        sc = __fadd_rn(fmaf(-2.f, a3, xsq), __ldg(&g_esq[kb + 96]));
        if (sc < bestv) { bestv = sc; besti = kb + 96; }
    }
    #pragma unroll
    for (int o = 16; o > 0; o >>= 1) {
        float ov = __shfl_xor_sync(0xffffffffu, bestv, o);
        int   oi = __shfl_xor_sync(0xffffffffu, besti, o);
        if (ov < bestv || (ov == bestv && oi < besti)) { bestv = ov; besti = oi; }
    }
    if (lane == 0) g_fidx[row] = besti;
}

// ---------------- kernel 4: gather, write q_st + indices ----------------
__global__ void vq_combine(const float* __restrict__ x, const float* __restrict__ E,
                           float* __restrict__ out) {
    int gw   = (blockIdx.x * blockDim.x + threadIdx.x) >> 5;  // one warp per token row
    int lane = threadIdx.x & 31;
    if (gw >= N_TOK) return;

    int bi = g_fidx[gw];
    const float* er = E + (size_t)bi * DIM;
    const float* xr = x + (size_t)gw * DIM;
    float* qr = out + (size_t)gw * DIM;
    float sq = 0.f;
    #pragma unroll
    for (int d = lane; d < DIM; d += 32) {
        float e  = er[d];
        float xv = xr[d];
        qr[d] = __fadd_rn(xv, __fadd_rn(e, -xv));  // straight-through: fl(x + fl(q - x))
        float df = __fadd_rn(xv, -e);
        sq = __fadd_rn(sq, __fmul_rn(df, df));
    }
    #pragma unroll
    for (int o = 16; o > 0; o >>= 1) sq = __fadd_rn(sq, __shfl_xor_sync(0xffffffffu, sq, o));
    if (lane == 0) {
        g_rowsq[gw] = sq;
        out[(size_t)N_TOK * DIM + gw] = (float)bi;   // indices as float32
    }
}

// ---------------- kernel 5: deterministic loss reduction ----------------
__global__ void vq_loss(float* __restrict__ out) {
    __shared__ float red[256];
    int t = threadIdx.x;
    float s = 0.f;
    for (int i = t; i < N_TOK; i += 256) s += g_rowsq[i];
    red[t] = s;
    __syncthreads();
    #pragma unroll
    for (int o = 128; o > 0; o >>= 1) {
        if (t < o) red[t] += red[t + o];
        __syncthreads();
    }
    if (t == 0) {
        float mse = red[0] / (float)((size_t)N_TOK * DIM);
        size_t base = (size_t)N_TOK * DIM + N_TOK;
        out[base + 0] = 0.25f * mse;   // commitment_loss
        out[base + 1] = mse;           // codebook_loss
        out[base + 2] = 1.25f * mse;   // total_loss
    }
}

// ---------------- entry point ----------------
extern "C" void kernel_launch(void* const* d_in, const int* in_sizes, int n_in,
                              void* d_out, int out_size) {
    (void)in_sizes; (void)n_in; (void)out_size;
    const float* x = (const float*)d_in[0];   // [32*256, 512]
    const float* E = (const float*)d_in[1];   // [8192, 512]
    float* out = (float*)d_out;

    vq_esq<<<K_CODES * 32 / 256, 256>>>(E);
    vq_xsq<<<N_TOK * 32 / 256, 256>>>(x);
    dim3 agrid(K_CODES / BN, N_TOK / BM);     // (64, 64)
    vq_approx<<<agrid, 256>>>(x, E);
    vq_exact<<<N_TOK / 8, 256>>>(x, E);
    vq_combine<<<N_TOK * 32 / 256, 256>>>(x, E, out);
    vq_loss<<<1, 256>>>(out);
}